// round 3
// baseline (speedup 1.0000x reference)
#include <cuda_runtime.h>
#include <math.h>

// Fixed problem shapes
#define BS     4
#define C_     64
#define H_     64
#define W_     64
#define HW     4096     // H*W
#define NPTS   4096
#define K_     3
#define M_TOT  (BS*HW)  // 16384

#define NSPLIT 16
#define PTS_PER_SPLIT (NPTS/NSPLIT)  // 256
#define QT 4                          // queries per thread in knn
#define KNN_THREADS 256

#define LRELU_SLOPE 0.1f

// ---------------- device scratch (no allocations allowed) ----------------
__device__ float g_f3t[BS * NPTS * C_];      // feat_3d transposed: [b][n][c]  (4 MB)
__device__ float g_pd[M_TOT * NSPLIT * 3];   // partial knn distances (3 MB)
__device__ int   g_pi[M_TOT * NSPLIT * 3];   // partial knn indices   (3 MB)
__device__ int   g_knn[M_TOT * 3];           // merged knn indices
__device__ float g_final[M_TOT * C_];        // [m][c] fused score*feat result (4 MB)

// ---------------- K1: transpose feat_3d (b,C,N) -> (b,N,C) ----------------
__global__ void transpose_f3(const float* __restrict__ f3) {
    __shared__ float tile[32][33];
    int b  = blockIdx.z;
    int c0 = blockIdx.y * 32;
    int n0 = blockIdx.x * 32;
    const float* src = f3 + ((size_t)(b * C_ + c0)) * NPTS + n0;
    #pragma unroll
    for (int i = threadIdx.y; i < 32; i += 8)
        tile[i][threadIdx.x] = src[i * NPTS + threadIdx.x];
    __syncthreads();
    float* dst = g_f3t + ((size_t)(b * NPTS + n0)) * C_ + c0;
    #pragma unroll
    for (int i = threadIdx.y; i < 32; i += 8)
        dst[i * C_ + threadIdx.x] = tile[threadIdx.x][i];
}

// ---------------- K2: partial KNN, 4 queries per thread ----------------
// dist2 rounding replicated vs reference (XLA K=2 GEMM FMA k-loop):
//   cross = fma(y, v, rn(x*u)); u2 = rn(rn(u*u)+rn(v*v));
//   d = rn(rn(g2+u2) - rn(2*cross))
// Queries strided by 256 within a 1024-query tile -> fx identical per thread,
// so rn(fx*u) is shared across the 4 queries (identical per-pair rounding).
__global__ void knn_partial(const float* __restrict__ uv) {
    __shared__ float4 spt[PTS_PER_SPLIT];   // (u, v, u2, pad)
    int b     = blockIdx.z;
    int split = blockIdx.y;
    int nbase = split * PTS_PER_SPLIT;
    const float* uvb = uv + (size_t)b * 2 * NPTS;

    for (int n = threadIdx.x; n < PTS_PER_SPLIT; n += KNN_THREADS) {
        float u = uvb[nbase + n];
        float v = uvb[NPTS + nbase + n];
        spt[n] = make_float4(u, v,
                             __fadd_rn(__fmul_rn(u, u), __fmul_rn(v, v)), 0.f);
    }
    __syncthreads();

    int q0 = blockIdx.x * (KNN_THREADS * QT) + threadIdx.x;
    float fx = (float)(q0 & 63);            // same for all QT queries (stride 256)
    float fy[QT], g2[QT];
    float d0[QT], d1[QT], d2[QT];
    int   i0[QT], i1[QT], i2[QT];
    #pragma unroll
    for (int k = 0; k < QT; k++) {
        int q = q0 + k * KNN_THREADS;
        fy[k] = (float)(q >> 6);
        g2[k] = fx * fx + fy[k] * fy[k];    // exact (small ints)
        d0[k] = 3.4e38f; d1[k] = 3.4e38f; d2[k] = 3.4e38f;
        i0[k] = 0; i1[k] = 0; i2[k] = 0;
    }

    #pragma unroll 2
    for (int n = 0; n < PTS_PER_SPLIT; n++) {
        float4 p = spt[n];
        float xu = __fmul_rn(fx, p.x);
        #pragma unroll
        for (int k = 0; k < QT; k++) {
            float cross = __fmaf_rn(fy[k], p.y, xu);
            float d = __fsub_rn(__fadd_rn(g2[k], p.z), __fadd_rn(cross, cross));
            if (d < d2[k]) {        // strict < => index-stable (matches top_k ties)
                if (d < d1[k]) {
                    d2[k] = d1[k]; i2[k] = i1[k];
                    if (d < d0[k]) { d1[k] = d0[k]; i1[k] = i0[k];
                                     d0[k] = d;     i0[k] = nbase + n; }
                    else           { d1[k] = d;     i1[k] = nbase + n; }
                } else { d2[k] = d; i2[k] = nbase + n; }
            }
        }
    }

    #pragma unroll
    for (int k = 0; k < QT; k++) {
        int q = q0 + k * KNN_THREADS;
        int m = b * HW + q;
        int base = (m * NSPLIT + split) * 3;
        g_pd[base] = d0[k]; g_pd[base + 1] = d1[k]; g_pd[base + 2] = d2[k];
        g_pi[base] = i0[k]; g_pi[base + 1] = i1[k]; g_pi[base + 2] = i2[k];
    }
}

// ---------------- K3: merge the 16 partial top-3 lists ----------------
__global__ void knn_merge() {
    int m = blockIdx.x * 256 + threadIdx.x;
    float d0 = 3.4e38f, d1 = 3.4e38f, d2 = 3.4e38f;
    int   i0 = 0, i1 = 0, i2 = 0;
    int base = m * NSPLIT * 3;
    #pragma unroll
    for (int r = 0; r < NSPLIT * 3; r++) {
        float d = g_pd[base + r];
        int   idx = g_pi[base + r];
        // splits visited in ascending index range, each list d-ascending with
        // index-stable ties; strict-< insertion reproduces the full streaming scan.
        if (d < d2) {
            if (d < d1) {
                d2 = d1; i2 = i1;
                if (d < d0) { d1 = d0; i1 = i0; d0 = d; i0 = idx; }
                else        { d1 = d;  i1 = idx; }
            } else { d2 = d; i2 = idx; }
        }
    }
    g_knn[m * 3] = i0; g_knn[m * 3 + 1] = i1; g_knn[m * 3 + 2] = i2;
}

// ---------------- K4: gather + score MLP + weighted sum ----------------
// One warp per query. lane -> channels (lane, lane+32).
// h[16 x 3] distributed: lane l holds h[i=l&15][j=l>>4] (ha) and h[i=l&15][j=2] (hb);
// broadcast via shfl in the w2 contraction.
#define QPW 2   // queries per warp (unrolled for ILP / latency hiding)
__global__ void score_kernel(const float* __restrict__ uv,
                             const float* __restrict__ w1, const float* __restrict__ b1,
                             const float* __restrict__ w2, const float* __restrict__ b2) {
    int lane = threadIdx.x & 31;
    int warp = blockIdx.x * (blockDim.x >> 5) + (threadIdx.x >> 5);
    int i_mine = lane & 15;
    int j_mine = lane >> 4;

    // hoisted weights
    float w1a = w1[i_mine * 3 + 0];
    float w1b = w1[i_mine * 3 + 1];
    float w1c = w1[i_mine * 3 + 2];
    float b1r = b1[i_mine];
    float w2lo[16], w2hi[16];
    #pragma unroll
    for (int i = 0; i < 16; i++) {
        w2lo[i] = w2[lane * 16 + i];
        w2hi[i] = w2[(lane + 32) * 16 + i];
    }
    float b2lo = b2[lane], b2hi = b2[lane + 32];

    #pragma unroll
    for (int t = 0; t < QPW; t++) {
        int m = warp * QPW + t;            // 0..16383
        int b = m >> 12;
        int q = m & 4095;
        float fx = (float)(q & 63);
        float fy = (float)(q >> 6);

        int n0 = __ldg(&g_knn[m * 3]);
        int n1 = __ldg(&g_knn[m * 3 + 1]);
        int n2 = __ldg(&g_knn[m * 3 + 2]);
        const float* uvb = uv + (size_t)b * 2 * NPTS;

        // issue the feature gathers early (independent of the MLP chain)
        const float* f0 = g_f3t + ((size_t)(b * NPTS + n0)) * C_;
        const float* f1 = g_f3t + ((size_t)(b * NPTS + n1)) * C_;
        const float* f2 = g_f3t + ((size_t)(b * NPTS + n2)) * C_;
        float f0lo = f0[lane], f0hi = f0[lane + 32];
        float f1lo = f1[lane], f1hi = f1[lane + 32];
        float f2lo = f2[lane], f2hi = f2[lane + 32];

        // h for my (i_mine, j_mine) neighbor
        int   na = j_mine ? n1 : n0;
        float ua = uvb[na], va = uvb[NPTS + na];
        float oxa = ua - fx, oya = va - fy;
        float nrma = sqrtf(oxa * oxa + oya * oya);
        float ha = fmaf(w1c, nrma, fmaf(w1b, oya, w1a * oxa)) + b1r;
        ha = ha >= 0.f ? ha : LRELU_SLOPE * ha;
        // h for (i_mine, j=2)
        float ub = uvb[n2], vb = uvb[NPTS + n2];
        float oxb = ub - fx, oyb = vb - fy;
        float nrmb = sqrtf(oxb * oxb + oyb * oyb);
        float hb = fmaf(w1c, nrmb, fmaf(w1b, oyb, w1a * oxb)) + b1r;
        hb = hb >= 0.f ? hb : LRELU_SLOPE * hb;

        float zlo0 = b2lo, zlo1 = b2lo, zlo2 = b2lo;
        float zhi0 = b2hi, zhi1 = b2hi, zhi2 = b2hi;
        #pragma unroll
        for (int i = 0; i < 16; i++) {
            float h0 = __shfl_sync(0xffffffffu, ha, i);
            float h1 = __shfl_sync(0xffffffffu, ha, 16 + i);
            float h2 = __shfl_sync(0xffffffffu, hb, i);
            zlo0 = fmaf(w2lo[i], h0, zlo0);
            zlo1 = fmaf(w2lo[i], h1, zlo1);
            zlo2 = fmaf(w2lo[i], h2, zlo2);
            zhi0 = fmaf(w2hi[i], h0, zhi0);
            zhi1 = fmaf(w2hi[i], h1, zhi1);
            zhi2 = fmaf(w2hi[i], h2, zhi2);
        }
        float s0lo = 1.f / (1.f + __expf(-zlo0));
        float s1lo = 1.f / (1.f + __expf(-zlo1));
        float s2lo = 1.f / (1.f + __expf(-zlo2));
        float s0hi = 1.f / (1.f + __expf(-zhi0));
        float s1hi = 1.f / (1.f + __expf(-zhi1));
        float s2hi = 1.f / (1.f + __expf(-zhi2));

        float flo = fmaf(s2lo, f2lo, fmaf(s1lo, f1lo, s0lo * f0lo));
        float fhi = fmaf(s2hi, f2hi, fmaf(s1hi, f1hi, s0hi * f0hi));

        g_final[(size_t)m * C_ + lane]      = flo;
        g_final[(size_t)m * C_ + lane + 32] = fhi;
    }
}

// ---------------- K5: out = lrelu(w_out @ final + b_out) ----------------
// Block: 256 threads = 8 o-groups (uniform per warp) x 32 m-lanes; m-tile = 128.
__global__ void out_gemm(const float* __restrict__ w_out,
                         const float* __restrict__ b_out,
                         float* __restrict__ out) {
    __shared__ float Wt[64 * 64];     // [c][o] for LDS.128 reads
    __shared__ float Fs[128 * 64];    // swizzled: row r, col (c+r)&63

    int tid = threadIdx.x;
    for (int idx = tid; idx < 4096; idx += 256) {
        int o = idx >> 6, c = idx & 63;
        Wt[c * 64 + o] = w_out[idx];
    }
    int m0 = blockIdx.x * 128;
    for (int idx = tid; idx < 8192; idx += 256) {
        int r = idx >> 6, c = idx & 63;
        Fs[r * 64 + ((c + r) & 63)] = g_final[(size_t)(m0 + r) * 64 + c];
    }
    __syncthreads();

    int mi = tid & 31;
    int og = tid >> 5;                 // uniform within warp -> broadcast LDS for W
    float acc[4][8];
    #pragma unroll
    for (int j = 0; j < 4; j++)
        #pragma unroll
        for (int oi = 0; oi < 8; oi++) acc[j][oi] = 0.f;

    #pragma unroll 8
    for (int c = 0; c < 64; c++) {
        float4 wv0 = *(const float4*)&Wt[c * 64 + og * 8];
        float4 wv1 = *(const float4*)&Wt[c * 64 + og * 8 + 4];
        #pragma unroll
        for (int j = 0; j < 4; j++) {
            int r = mi + 32 * j;
            float f = Fs[r * 64 + ((c + r) & 63)];
            acc[j][0] = fmaf(wv0.x, f, acc[j][0]);
            acc[j][1] = fmaf(wv0.y, f, acc[j][1]);
            acc[j][2] = fmaf(wv0.z, f, acc[j][2]);
            acc[j][3] = fmaf(wv0.w, f, acc[j][3]);
            acc[j][4] = fmaf(wv1.x, f, acc[j][4]);
            acc[j][5] = fmaf(wv1.y, f, acc[j][5]);
            acc[j][6] = fmaf(wv1.z, f, acc[j][6]);
            acc[j][7] = fmaf(wv1.w, f, acc[j][7]);
        }
    }
    #pragma unroll
    for (int oi = 0; oi < 8; oi++) {
        int o = og * 8 + oi;
        float bo = __ldg(&b_out[o]);
        #pragma unroll
        for (int j = 0; j < 4; j++) {
            int m = m0 + mi + 32 * j;
            int b = m >> 12;
            int q = m & 4095;
            float v = acc[j][oi] + bo;
            v = v >= 0.f ? v : LRELU_SLOPE * v;
            out[((size_t)(b * 64 + o) << 12) + q] = v;
        }
    }
}

// ---------------- launch ----------------
extern "C" void kernel_launch(void* const* d_in, const int* in_sizes, int n_in,
                              void* d_out, int out_size) {
    const float* uv      = (const float*)d_in[0];
    // d_in[1] = feat_2d: shape-only in reference, unused
    const float* feat_3d = (const float*)d_in[2];
    const float* w1      = (const float*)d_in[3];
    const float* b1      = (const float*)d_in[4];
    const float* w2      = (const float*)d_in[5];
    const float* b2      = (const float*)d_in[6];
    const float* w_out   = (const float*)d_in[7];
    const float* b_out   = (const float*)d_in[8];
    float* out = (float*)d_out;

    transpose_f3<<<dim3(NPTS / 32, C_ / 32, BS), dim3(32, 8)>>>(feat_3d);
    knn_partial<<<dim3(HW / (KNN_THREADS * QT), NSPLIT, BS), KNN_THREADS>>>(uv);
    knn_merge<<<M_TOT / 256, 256>>>();
    score_kernel<<<M_TOT / (QPW * 8), 256>>>(uv, w1, b1, w2, b2);
    out_gemm<<<M_TOT / 128, 256>>>(w_out, b_out, out);
}

// round 4
// speedup vs baseline: 1.5593x; 1.5593x over previous
#include <cuda_runtime.h>
#include <math.h>

// Fixed problem shapes
#define BS     4
#define C_     64
#define H_     64
#define W_     64
#define HW     4096     // H*W
#define NPTS   4096
#define M_TOT  (BS*HW)  // 16384

#define CELL   4
#define GRIDC  16       // 64/CELL
#define NCELL  (GRIDC*GRIDC)

#define LRELU_SLOPE 0.1f

// ---------------- device scratch (no allocations allowed) ----------------
__device__ float  g_f3t[BS * NPTS * C_];       // feat_3d transposed [b][n][c] (4 MB)
__device__ float4 g_cpts[BS * NPTS];           // binned points (u,v,u2,idx)  (256 KB)
__device__ int    g_cstart[BS][NCELL + 1];     // cell start offsets
__device__ int    g_knn[M_TOT * 3];            // knn indices
__device__ float  g_final[M_TOT * C_];         // [m][c] score*feat result (4 MB)

// ---------------- K1: transpose feat_3d (b,C,N) -> (b,N,C) ----------------
__global__ void transpose_f3(const float* __restrict__ f3) {
    __shared__ float tile[32][33];
    int b  = blockIdx.z;
    int c0 = blockIdx.y * 32;
    int n0 = blockIdx.x * 32;
    const float* src = f3 + ((size_t)(b * C_ + c0)) * NPTS + n0;
    #pragma unroll
    for (int i = threadIdx.y; i < 32; i += 8)
        tile[i][threadIdx.x] = src[i * NPTS + threadIdx.x];
    __syncthreads();
    float* dst = g_f3t + ((size_t)(b * NPTS + n0)) * C_ + c0;
    #pragma unroll
    for (int i = threadIdx.y; i < 32; i += 8)
        dst[i * C_ + threadIdx.x] = tile[threadIdx.x][i];
}

// ---------------- K2: bin points into 16x16 cells (counting sort) ----------------
// cell = floor(u/4): u in [0,64), u*0.25f is exact (power-of-2 scale) -> cast == floor.
__global__ void bin_points(const float* __restrict__ uv) {
    __shared__ int cnt[NCELL];
    __shared__ int off[NCELL];
    __shared__ int sA[NCELL], sB[NCELL];
    int b = blockIdx.x;
    int t = threadIdx.x;          // 256
    const float* uvb = uv + (size_t)b * 2 * NPTS;

    cnt[t] = 0;
    __syncthreads();

    int mycell[16];
    #pragma unroll
    for (int i = 0; i < 16; i++) {
        int n = t + i * 256;
        float u = uvb[n], v = uvb[NPTS + n];
        int cx = (int)(u * 0.25f);
        int cy = (int)(v * 0.25f);
        int c = cy * GRIDC + cx;
        mycell[i] = c;
        atomicAdd(&cnt[c], 1);
    }
    __syncthreads();

    // inclusive scan (Hillis-Steele, double buffer)
    sA[t] = cnt[t];
    __syncthreads();
    int* src = sA; int* dst = sB;
    #pragma unroll
    for (int ofs = 1; ofs < NCELL; ofs <<= 1) {
        int v = src[t];
        if (t >= ofs) v += src[t - ofs];
        dst[t] = v;
        __syncthreads();
        int* tmp = src; src = dst; dst = tmp;
    }
    int excl = src[t] - cnt[t];
    off[t] = excl;
    g_cstart[b][t] = excl;
    if (t == NCELL - 1) g_cstart[b][NCELL] = src[NCELL - 1];
    __syncthreads();

    #pragma unroll
    for (int i = 0; i < 16; i++) {
        int n = t + i * 256;
        int c = mycell[i];
        int pos = atomicAdd(&off[c], 1);
        float u = uvb[n], v = uvb[NPTS + n];
        g_cpts[(size_t)b * NPTS + pos] =
            make_float4(u, v,
                        __fadd_rn(__fmul_rn(u, u), __fmul_rn(v, v)),
                        __int_as_float(n));
    }
}

// ---------------- K3: ring-search KNN (one thread per query) ----------------
// d rounding identical to the validated brute force:
//   cross = fma(fy, v, rn(fx*u)); d = rn(rn(g2+u2) - rn(2*cross))
// Selection tie-breaks on (d, idx) lexicographic -> matches top_k lowest-index
// ties and is deterministic under nondeterministic in-cell scatter order.
__global__ void knn_search() {
    int q = blockIdx.x * blockDim.x + threadIdx.x;   // 0..16383
    int b  = q >> 12;
    int qq = q & 4095;
    int px = qq & 63, py = qq >> 6;
    float fx = (float)px, fy = (float)py;
    float g2 = fx * fx + fy * fy;                    // exact (small ints)
    int cx = px >> 2, cy = py >> 2;

    float d0 = 3.4e38f, d1 = 3.4e38f, d2 = 3.4e38f;
    int   i0 = 0x7fffffff, i1 = 0x7fffffff, i2 = 0x7fffffff;

    const float4* pts = g_cpts + (size_t)b * NPTS;
    const int*    cs  = g_cstart[b];

    #define SCAN_RANGE(s_, e_)                                                  \
        for (int p = (s_); p < (e_); p++) {                                     \
            float4 P = pts[p];                                                  \
            float cross = __fmaf_rn(fy, P.y, __fmul_rn(fx, P.x));               \
            float d = __fsub_rn(__fadd_rn(g2, P.z), __fadd_rn(cross, cross));   \
            int idx = __float_as_int(P.w);                                      \
            if (d < d2 || (d == d2 && idx < i2)) {                              \
                if (d < d1 || (d == d1 && idx < i1)) {                          \
                    d2 = d1; i2 = i1;                                           \
                    if (d < d0 || (d == d0 && idx < i0)) {                      \
                        d1 = d0; i1 = i0; d0 = d; i0 = idx;                     \
                    } else { d1 = d; i1 = idx; }                                \
                } else { d2 = d; i2 = idx; }                                    \
            }                                                                   \
        }

    for (int rc = 0; rc < GRIDC; rc++) {
        // geometric lower bound to ring rc: (CELL*(rc-1))^2 ; margin >> fp error
        float lb = (float)(CELL * (rc - 1));
        if (rc >= 1 && lb * lb > d2 + 0.5f) break;   // false while d2 = INF
        int xlo = max(cx - rc, 0), xhi = min(cx + rc, GRIDC - 1);
        int ylo = max(cy - rc, 0), yhi = min(cy + rc, GRIDC - 1);
        for (int y = ylo; y <= yhi; y++) {
            if (y == cy - rc || y == cy + rc) {
                // full row of the ring: cells contiguous in memory
                SCAN_RANGE(cs[y * GRIDC + xlo], cs[y * GRIDC + xhi + 1]);
            } else {
                if (cx - rc >= 0) {
                    int c = y * GRIDC + (cx - rc);
                    SCAN_RANGE(cs[c], cs[c + 1]);
                }
                if (cx + rc <= GRIDC - 1) {
                    int c = y * GRIDC + (cx + rc);
                    SCAN_RANGE(cs[c], cs[c + 1]);
                }
            }
        }
    }
    #undef SCAN_RANGE

    int m = q;
    g_knn[m * 3] = i0; g_knn[m * 3 + 1] = i1; g_knn[m * 3 + 2] = i2;
}

// ---------------- K4: gather + score MLP + weighted sum (R2 version) ----------------
// One warp per query. lane -> channels (lane, lane+32).
// h[16 x 3] distributed: lane l holds h[i=l&15][j=l>>4] (ha) and h[i=l&15][j=2] (hb);
// broadcast via shfl in the w2 contraction.
#define QPW 4   // queries per warp
__global__ void score_kernel(const float* __restrict__ uv,
                             const float* __restrict__ w1, const float* __restrict__ b1,
                             const float* __restrict__ w2, const float* __restrict__ b2) {
    int lane = threadIdx.x & 31;
    int warp = blockIdx.x * (blockDim.x >> 5) + (threadIdx.x >> 5);   // 0..4095
    int i_mine = lane & 15;
    int j_mine = lane >> 4;

    // hoisted weights
    float w1a = w1[i_mine * 3 + 0];
    float w1b = w1[i_mine * 3 + 1];
    float w1c = w1[i_mine * 3 + 2];
    float b1r = b1[i_mine];
    float w2lo[16], w2hi[16];
    #pragma unroll
    for (int i = 0; i < 16; i++) {
        w2lo[i] = w2[lane * 16 + i];
        w2hi[i] = w2[(lane + 32) * 16 + i];
    }
    float b2lo = b2[lane], b2hi = b2[lane + 32];

    for (int t = 0; t < QPW; t++) {
        int m = warp * QPW + t;            // 0..16383
        int b = m >> 12;
        int q = m & 4095;
        float fx = (float)(q & 63);
        float fy = (float)(q >> 6);

        int n0 = g_knn[m * 3];
        int n1 = g_knn[m * 3 + 1];
        int n2 = g_knn[m * 3 + 2];
        const float* uvb = uv + (size_t)b * 2 * NPTS;

        // h for my (i_mine, j_mine) neighbor
        int   na = j_mine ? n1 : n0;
        float ua = uvb[na], va = uvb[NPTS + na];
        float oxa = ua - fx, oya = va - fy;
        float nrma = sqrtf(oxa * oxa + oya * oya);
        float ha = fmaf(w1c, nrma, fmaf(w1b, oya, w1a * oxa)) + b1r;
        ha = ha >= 0.f ? ha : LRELU_SLOPE * ha;
        // h for (i_mine, j=2)
        float ub = uvb[n2], vb = uvb[NPTS + n2];
        float oxb = ub - fx, oyb = vb - fy;
        float nrmb = sqrtf(oxb * oxb + oyb * oyb);
        float hb = fmaf(w1c, nrmb, fmaf(w1b, oyb, w1a * oxb)) + b1r;
        hb = hb >= 0.f ? hb : LRELU_SLOPE * hb;

        float zlo0 = b2lo, zlo1 = b2lo, zlo2 = b2lo;
        float zhi0 = b2hi, zhi1 = b2hi, zhi2 = b2hi;
        #pragma unroll
        for (int i = 0; i < 16; i++) {
            float h0 = __shfl_sync(0xffffffffu, ha, i);
            float h1 = __shfl_sync(0xffffffffu, ha, 16 + i);
            float h2 = __shfl_sync(0xffffffffu, hb, i);
            zlo0 = fmaf(w2lo[i], h0, zlo0);
            zlo1 = fmaf(w2lo[i], h1, zlo1);
            zlo2 = fmaf(w2lo[i], h2, zlo2);
            zhi0 = fmaf(w2hi[i], h0, zhi0);
            zhi1 = fmaf(w2hi[i], h1, zhi1);
            zhi2 = fmaf(w2hi[i], h2, zhi2);
        }
        float s0lo = 1.f / (1.f + __expf(-zlo0));
        float s1lo = 1.f / (1.f + __expf(-zlo1));
        float s2lo = 1.f / (1.f + __expf(-zlo2));
        float s0hi = 1.f / (1.f + __expf(-zhi0));
        float s1hi = 1.f / (1.f + __expf(-zhi1));
        float s2hi = 1.f / (1.f + __expf(-zhi2));

        const float* f0 = g_f3t + ((size_t)(b * NPTS + n0)) * C_;
        const float* f1 = g_f3t + ((size_t)(b * NPTS + n1)) * C_;
        const float* f2 = g_f3t + ((size_t)(b * NPTS + n2)) * C_;
        float flo = fmaf(s2lo, f2[lane], fmaf(s1lo, f1[lane], s0lo * f0[lane]));
        float fhi = fmaf(s2hi, f2[lane + 32], fmaf(s1hi, f1[lane + 32], s0hi * f0[lane + 32]));

        g_final[(size_t)m * C_ + lane]      = flo;
        g_final[(size_t)m * C_ + lane + 32] = fhi;
    }
}

// ---------------- K5: out = lrelu(w_out @ final + b_out) ----------------
// Block: 256 threads = 8 o-groups (uniform per warp) x 32 m-lanes; m-tile = 128.
__global__ void out_gemm(const float* __restrict__ w_out,
                         const float* __restrict__ b_out,
                         float* __restrict__ out) {
    __shared__ float Wt[64 * 64];     // [c][o] for LDS.128 reads
    __shared__ float Fs[128 * 64];    // swizzled: row r, col (c+r)&63

    int tid = threadIdx.x;
    for (int idx = tid; idx < 4096; idx += 256) {
        int o = idx >> 6, c = idx & 63;
        Wt[c * 64 + o] = w_out[idx];
    }
    int m0 = blockIdx.x * 128;
    for (int idx = tid; idx < 8192; idx += 256) {
        int r = idx >> 6, c = idx & 63;
        Fs[r * 64 + ((c + r) & 63)] = g_final[(size_t)(m0 + r) * 64 + c];
    }
    __syncthreads();

    int mi = tid & 31;
    int og = tid >> 5;                 // uniform within warp -> broadcast LDS for W
    float acc[4][8];
    #pragma unroll
    for (int j = 0; j < 4; j++)
        #pragma unroll
        for (int oi = 0; oi < 8; oi++) acc[j][oi] = 0.f;

    #pragma unroll 8
    for (int c = 0; c < 64; c++) {
        float4 wv0 = *(const float4*)&Wt[c * 64 + og * 8];
        float4 wv1 = *(const float4*)&Wt[c * 64 + og * 8 + 4];
        #pragma unroll
        for (int j = 0; j < 4; j++) {
            int r = mi + 32 * j;
            float f = Fs[r * 64 + ((c + r) & 63)];
            acc[j][0] = fmaf(wv0.x, f, acc[j][0]);
            acc[j][1] = fmaf(wv0.y, f, acc[j][1]);
            acc[j][2] = fmaf(wv0.z, f, acc[j][2]);
            acc[j][3] = fmaf(wv0.w, f, acc[j][3]);
            acc[j][4] = fmaf(wv1.x, f, acc[j][4]);
            acc[j][5] = fmaf(wv1.y, f, acc[j][5]);
            acc[j][6] = fmaf(wv1.z, f, acc[j][6]);
            acc[j][7] = fmaf(wv1.w, f, acc[j][7]);
        }
    }
    #pragma unroll
    for (int oi = 0; oi < 8; oi++) {
        int o = og * 8 + oi;
        float bo = __ldg(&b_out[o]);
        #pragma unroll
        for (int j = 0; j < 4; j++) {
            int m = m0 + mi + 32 * j;
            int b = m >> 12;
            int q = m & 4095;
            float v = acc[j][oi] + bo;
            v = v >= 0.f ? v : LRELU_SLOPE * v;
            out[((size_t)(b * 64 + o) << 12) + q] = v;
        }
    }
}

// ---------------- launch ----------------
extern "C" void kernel_launch(void* const* d_in, const int* in_sizes, int n_in,
                              void* d_out, int out_size) {
    const float* uv      = (const float*)d_in[0];
    // d_in[1] = feat_2d: shape-only in reference, unused
    const float* feat_3d = (const float*)d_in[2];
    const float* w1      = (const float*)d_in[3];
    const float* b1      = (const float*)d_in[4];
    const float* w2      = (const float*)d_in[5];
    const float* b2      = (const float*)d_in[6];
    const float* w_out   = (const float*)d_in[7];
    const float* b_out   = (const float*)d_in[8];
    float* out = (float*)d_out;

    transpose_f3<<<dim3(NPTS / 32, C_ / 32, BS), dim3(32, 8)>>>(feat_3d);
    bin_points<<<BS, 256>>>(uv);
    knn_search<<<M_TOT / 256, 256>>>();
    score_kernel<<<M_TOT / (QPW * 8), 256>>>(uv, w1, b1, w2, b2);
    out_gemm<<<M_TOT / 128, 256>>>(w_out, b_out, out);
}

// round 6
// speedup vs baseline: 2.0858x; 1.3377x over previous
#include <cuda_runtime.h>
#include <math.h>

// Fixed problem shapes
#define BS     4
#define C_     64
#define H_     64
#define W_     64
#define HW     4096     // H*W
#define NPTS   4096
#define M_TOT  (BS*HW)  // 16384

#define CELL   4
#define GRIDC  16       // 64/CELL
#define NCELL  (GRIDC*GRIDC)
#define CAND_CAP 768    // smem candidate cap (expected ~144)

#define LRELU_SLOPE 0.1f

// ---------------- device scratch (no allocations allowed) ----------------
__device__ float  g_f3t[BS * NPTS * C_];       // feat_3d transposed [b][n][c] (4 MB)
__device__ float4 g_cpts[BS * NPTS];           // binned points (u,v,u2,idx)  (256 KB)
__device__ int    g_cstart[BS][NCELL + 1];     // cell start offsets
__device__ int    g_knn[M_TOT * 3];            // knn indices
__device__ float  g_final[M_TOT * C_];         // [m][c] score*feat result (4 MB)

// ---------------- K1: transpose feat_3d (b,C,N) -> (b,N,C) ----------------
__global__ void transpose_f3(const float* __restrict__ f3) {
    __shared__ float tile[32][33];
    int b  = blockIdx.z;
    int c0 = blockIdx.y * 32;
    int n0 = blockIdx.x * 32;
    const float* src = f3 + ((size_t)(b * C_ + c0)) * NPTS + n0;
    #pragma unroll
    for (int i = threadIdx.y; i < 32; i += 8)
        tile[i][threadIdx.x] = src[i * NPTS + threadIdx.x];
    __syncthreads();
    float* dst = g_f3t + ((size_t)(b * NPTS + n0)) * C_ + c0;
    #pragma unroll
    for (int i = threadIdx.y; i < 32; i += 8)
        dst[i * C_ + threadIdx.x] = tile[threadIdx.x][i];
}

// ---------------- K2: bin points into 16x16 cells (counting sort) ----------------
__global__ void bin_points(const float* __restrict__ uv) {
    __shared__ int cnt[NCELL];
    __shared__ int off[NCELL];
    __shared__ int sA[NCELL], sB[NCELL];
    int b = blockIdx.x;
    int t = threadIdx.x;          // 256
    const float* uvb = uv + (size_t)b * 2 * NPTS;

    cnt[t] = 0;
    __syncthreads();

    int mycell[16];
    #pragma unroll
    for (int i = 0; i < 16; i++) {
        int n = t + i * 256;
        float u = uvb[n], v = uvb[NPTS + n];
        int cx = (int)(u * 0.25f);
        int cy = (int)(v * 0.25f);
        int c = cy * GRIDC + cx;
        mycell[i] = c;
        atomicAdd(&cnt[c], 1);
    }
    __syncthreads();

    // inclusive scan (Hillis-Steele, double buffer)
    sA[t] = cnt[t];
    __syncthreads();
    int* src = sA; int* dst = sB;
    #pragma unroll
    for (int ofs = 1; ofs < NCELL; ofs <<= 1) {
        int v = src[t];
        if (t >= ofs) v += src[t - ofs];
        dst[t] = v;
        __syncthreads();
        int* tmp = src; src = dst; dst = tmp;
    }
    int excl = src[t] - cnt[t];
    off[t] = excl;
    g_cstart[b][t] = excl;
    if (t == NCELL - 1) g_cstart[b][NCELL] = src[NCELL - 1];
    __syncthreads();

    #pragma unroll
    for (int i = 0; i < 16; i++) {
        int n = t + i * 256;
        int c = mycell[i];
        int pos = atomicAdd(&off[c], 1);
        float u = uvb[n], v = uvb[NPTS + n];
        g_cpts[(size_t)b * NPTS + pos] =
            make_float4(u, v,
                        __fadd_rn(__fmul_rn(u, u), __fmul_rn(v, v)),
                        __int_as_float(n));
    }
}

// ---------------- K3: warp-cooperative KNN ----------------
// One block per (b, cell): 16 queries, 8 threads each.
// d rounding identical to validated version:
//   cross = fma(fy, v, rn(fx*u)); d = rn(rn(g2+u2) - rn(2*cross))
// Selection: (d, idx) lexicographic -> order-independent, matches top_k ties.
#define INS(dv, iv)                                                     \
    if ((dv) < d2 || ((dv) == d2 && (iv) < i2)) {                       \
        if ((dv) < d1 || ((dv) == d1 && (iv) < i1)) {                   \
            d2 = d1; i2 = i1;                                           \
            if ((dv) < d0 || ((dv) == d0 && (iv) < i0)) {               \
                d1 = d0; i1 = i0; d0 = (dv); i0 = (iv);                 \
            } else { d1 = (dv); i1 = (iv); }                            \
        } else { d2 = (dv); i2 = (iv); }                                \
    }

__global__ void knn_search() {
    __shared__ float4 cand[CAND_CAP];
    __shared__ int s_total;

    int b    = blockIdx.y;
    int cell = blockIdx.x;
    int cx = cell & (GRIDC - 1), cy = cell >> 4;
    int tid = threadIdx.x;          // 128

    const float4* pts = g_cpts + (size_t)b * NPTS;
    const int*    cs  = g_cstart[b];

    // ---- stage 3x3 neighborhood into smem ----
    int xlo = max(cx - 1, 0), xhi = min(cx + 1, GRIDC - 1);
    int ylo = max(cy - 1, 0), yhi = min(cy + 1, GRIDC - 1);
    int rs[3], rc_[3], rb[3], nrows = 0, total = 0;
    for (int y = ylo; y <= yhi; y++) {
        int s = cs[y * GRIDC + xlo];
        int e = cs[y * GRIDC + xhi + 1];
        rs[nrows] = s; rc_[nrows] = e - s; rb[nrows] = total;
        total += e - s; nrows++;
    }
    bool fits = (total <= CAND_CAP);
    if (fits) {
        for (int k = 0; k < nrows; k++)
            for (int i = tid; i < rc_[k]; i += 128)
                cand[rb[k] + i] = pts[rs[k] + i];
    }
    if (tid == 0) s_total = total;
    __syncthreads();

    // ---- per-query scan: group g = query, 8 threads/query ----
    int g   = tid >> 3;             // 0..15
    int sub = tid & 7;
    int px = cx * CELL + (g & 3);
    int py = cy * CELL + (g >> 2);
    float fx = (float)px, fy = (float)py;
    float g2 = fx * fx + fy * fy;   // exact (small ints)

    float d0 = 3.4e38f, d1 = 3.4e38f, d2 = 3.4e38f;
    int   i0 = 0x7fffffff, i1 = 0x7fffffff, i2 = 0x7fffffff;

    if (fits) {
        int T = s_total;
        for (int p = sub; p < T; p += 8) {
            float4 P = cand[p];
            float cross = __fmaf_rn(fy, P.y, __fmul_rn(fx, P.x));
            float d = __fsub_rn(__fadd_rn(g2, P.z), __fadd_rn(cross, cross));
            int idx = __float_as_int(P.w);
            INS(d, idx);
        }
    } else {
        // overflow slow path: scan gmem ranges directly (never hit in practice)
        for (int k = 0; k < nrows; k++)
            for (int p = sub; p < rc_[k]; p += 8) {
                float4 P = pts[rs[k] + p];
                float cross = __fmaf_rn(fy, P.y, __fmul_rn(fx, P.x));
                float d = __fsub_rn(__fadd_rn(g2, P.z), __fadd_rn(cross, cross));
                int idx = __float_as_int(P.w);
                INS(d, idx);
            }
    }

    // ---- merge 8 partial top-3 lists (shfl-down tree, width 8) ----
    #pragma unroll
    for (int off = 4; off > 0; off >>= 1) {
        float e0 = __shfl_down_sync(0xffffffffu, d0, off, 8);
        int   j0 = __shfl_down_sync(0xffffffffu, i0, off, 8);
        float e1 = __shfl_down_sync(0xffffffffu, d1, off, 8);
        int   j1 = __shfl_down_sync(0xffffffffu, i1, off, 8);
        float e2 = __shfl_down_sync(0xffffffffu, d2, off, 8);
        int   j2 = __shfl_down_sync(0xffffffffu, i2, off, 8);
        INS(e0, j0);
        INS(e1, j1);
        INS(e2, j2);
    }

    if (sub == 0) {
        // ---- rare fallback: rings >= 2, same bound as validated version ----
        for (int rc = 2; rc < GRIDC; rc++) {
            float lb = (float)(CELL * (rc - 1));
            if (lb * lb > d2 + 0.5f) break;   // false while d2 = INF
            int Xlo = max(cx - rc, 0), Xhi = min(cx + rc, GRIDC - 1);
            int Ylo = max(cy - rc, 0), Yhi = min(cy + rc, GRIDC - 1);
            for (int y = Ylo; y <= Yhi; y++) {
                int ps, pe;
                if (y == cy - rc || y == cy + rc) {
                    ps = cs[y * GRIDC + Xlo]; pe = cs[y * GRIDC + Xhi + 1];
                    for (int p = ps; p < pe; p++) {
                        float4 P = pts[p];
                        float cross = __fmaf_rn(fy, P.y, __fmul_rn(fx, P.x));
                        float d = __fsub_rn(__fadd_rn(g2, P.z), __fadd_rn(cross, cross));
                        int idx = __float_as_int(P.w);
                        INS(d, idx);
                    }
                } else {
                    if (cx - rc >= 0) {
                        int c = y * GRIDC + (cx - rc);
                        for (int p = cs[c]; p < cs[c + 1]; p++) {
                            float4 P = pts[p];
                            float cross = __fmaf_rn(fy, P.y, __fmul_rn(fx, P.x));
                            float d = __fsub_rn(__fadd_rn(g2, P.z), __fadd_rn(cross, cross));
                            int idx = __float_as_int(P.w);
                            INS(d, idx);
                        }
                    }
                    if (cx + rc <= GRIDC - 1) {
                        int c = y * GRIDC + (cx + rc);
                        for (int p = cs[c]; p < cs[c + 1]; p++) {
                            float4 P = pts[p];
                            float cross = __fmaf_rn(fy, P.y, __fmul_rn(fx, P.x));
                            float d = __fsub_rn(__fadd_rn(g2, P.z), __fadd_rn(cross, cross));
                            int idx = __float_as_int(P.w);
                            INS(d, idx);
                        }
                    }
                }
            }
        }
        int m = b * HW + py * 64 + px;
        g_knn[m * 3] = i0; g_knn[m * 3 + 1] = i1; g_knn[m * 3 + 2] = i2;
    }
}
#undef INS

// ---------------- K4: gather + score MLP + weighted sum ----------------
// One warp per query. lane -> channels (lane, lane+32).
// h[3][16] broadcast via smem (replaces 48-shfl chain).
#define QPW 4   // queries per warp
__global__ void score_kernel(const float* __restrict__ uv,
                             const float* __restrict__ w1, const float* __restrict__ b1,
                             const float* __restrict__ w2, const float* __restrict__ b2) {
    __shared__ float hsm[8][48];      // per-warp h buffer: [j*16+i]
    int lane = threadIdx.x & 31;
    int wid  = threadIdx.x >> 5;
    int warp = blockIdx.x * (blockDim.x >> 5) + wid;   // 0..4095
    int i_mine = lane & 15;
    int j_mine = lane >> 4;

    // hoisted weights
    float w1a = w1[i_mine * 3 + 0];
    float w1b = w1[i_mine * 3 + 1];
    float w1c = w1[i_mine * 3 + 2];
    float b1r = b1[i_mine];
    float w2lo[16], w2hi[16];
    #pragma unroll
    for (int i = 0; i < 16; i++) {
        w2lo[i] = w2[lane * 16 + i];
        w2hi[i] = w2[(lane + 32) * 16 + i];
    }
    float b2lo = b2[lane], b2hi = b2[lane + 32];

    for (int t = 0; t < QPW; t++) {
        int m = warp * QPW + t;            // 0..16383
        int b = m >> 12;
        int q = m & 4095;
        float fx = (float)(q & 63);
        float fy = (float)(q >> 6);

        int n0 = g_knn[m * 3];
        int n1 = g_knn[m * 3 + 1];
        int n2 = g_knn[m * 3 + 2];
        const float* uvb = uv + (size_t)b * 2 * NPTS;

        // issue feature gathers early (independent of the MLP chain)
        const float* f0 = g_f3t + ((size_t)(b * NPTS + n0)) * C_;
        const float* f1 = g_f3t + ((size_t)(b * NPTS + n1)) * C_;
        const float* f2 = g_f3t + ((size_t)(b * NPTS + n2)) * C_;
        float f0lo = f0[lane], f0hi = f0[lane + 32];
        float f1lo = f1[lane], f1hi = f1[lane + 32];
        float f2lo = f2[lane], f2hi = f2[lane + 32];

        // h for my (i_mine, j_mine) neighbor
        int   na = j_mine ? n1 : n0;
        float ua = uvb[na], va = uvb[NPTS + na];
        float oxa = ua - fx, oya = va - fy;
        float nrma = sqrtf(oxa * oxa + oya * oya);
        float ha = fmaf(w1c, nrma, fmaf(w1b, oya, w1a * oxa)) + b1r;
        ha = ha >= 0.f ? ha : LRELU_SLOPE * ha;
        // h for (i_mine, j=2)
        float ub = uvb[n2], vb = uvb[NPTS + n2];
        float oxb = ub - fx, oyb = vb - fy;
        float nrmb = sqrtf(oxb * oxb + oyb * oyb);
        float hb = fmaf(w1c, nrmb, fmaf(w1b, oyb, w1a * oxb)) + b1r;
        hb = hb >= 0.f ? hb : LRELU_SLOPE * hb;

        hsm[wid][j_mine * 16 + i_mine] = ha;
        if (lane < 16) hsm[wid][32 + lane] = hb;
        __syncwarp();

        // z[j] = b2 + sum_i w2[:,i] * h[j][i]   (i ascending: same rounding as before)
        float z[3][2];
        #pragma unroll
        for (int j = 0; j < 3; j++) {
            float zlo = b2lo, zhi = b2hi;
            #pragma unroll
            for (int w = 0; w < 4; w++) {
                float4 hv = *(const float4*)&hsm[wid][j * 16 + w * 4];
                zlo = fmaf(w2lo[w * 4 + 0], hv.x, zlo);
                zlo = fmaf(w2lo[w * 4 + 1], hv.y, zlo);
                zlo = fmaf(w2lo[w * 4 + 2], hv.z, zlo);
                zlo = fmaf(w2lo[w * 4 + 3], hv.w, zlo);
                zhi = fmaf(w2hi[w * 4 + 0], hv.x, zhi);
                zhi = fmaf(w2hi[w * 4 + 1], hv.y, zhi);
                zhi = fmaf(w2hi[w * 4 + 2], hv.z, zhi);
                zhi = fmaf(w2hi[w * 4 + 3], hv.w, zhi);
            }
            z[j][0] = zlo; z[j][1] = zhi;
        }
        __syncwarp();

        float s0lo = 1.f / (1.f + __expf(-z[0][0]));
        float s1lo = 1.f / (1.f + __expf(-z[1][0]));
        float s2lo = 1.f / (1.f + __expf(-z[2][0]));
        float s0hi = 1.f / (1.f + __expf(-z[0][1]));
        float s1hi = 1.f / (1.f + __expf(-z[1][1]));
        float s2hi = 1.f / (1.f + __expf(-z[2][1]));

        float flo = fmaf(s2lo, f2lo, fmaf(s1lo, f1lo, s0lo * f0lo));
        float fhi = fmaf(s2hi, f2hi, fmaf(s1hi, f1hi, s0hi * f0hi));

        g_final[(size_t)m * C_ + lane]      = flo;
        g_final[(size_t)m * C_ + lane + 32] = fhi;
    }
}

// ---------------- K5: out = lrelu(w_out @ final + b_out) ----------------
__global__ void out_gemm(const float* __restrict__ w_out,
                         const float* __restrict__ b_out,
                         float* __restrict__ out) {
    __shared__ float Wt[64 * 64];     // [c][o] for LDS.128 reads
    __shared__ float Fs[128 * 64];    // swizzled: row r, col (c+r)&63

    int tid = threadIdx.x;
    for (int idx = tid; idx < 4096; idx += 256) {
        int o = idx >> 6, c = idx & 63;
        Wt[c * 64 + o] = w_out[idx];
    }
    int m0 = blockIdx.x * 128;
    for (int idx = tid; idx < 8192; idx += 256) {
        int r = idx >> 6, c = idx & 63;
        Fs[r * 64 + ((c + r) & 63)] = g_final[(size_t)(m0 + r) * 64 + c];
    }
    __syncthreads();

    int mi = tid & 31;
    int og = tid >> 5;                 // uniform within warp -> broadcast LDS for W
    float acc[4][8];
    #pragma unroll
    for (int j = 0; j < 4; j++)
        #pragma unroll
        for (int oi = 0; oi < 8; oi++) acc[j][oi] = 0.f;

    #pragma unroll 8
    for (int c = 0; c < 64; c++) {
        float4 wv0 = *(const float4*)&Wt[c * 64 + og * 8];
        float4 wv1 = *(const float4*)&Wt[c * 64 + og * 8 + 4];
        #pragma unroll
        for (int j = 0; j < 4; j++) {
            int r = mi + 32 * j;
            float f = Fs[r * 64 + ((c + r) & 63)];
            acc[j][0] = fmaf(wv0.x, f, acc[j][0]);
            acc[j][1] = fmaf(wv0.y, f, acc[j][1]);
            acc[j][2] = fmaf(wv0.z, f, acc[j][2]);
            acc[j][3] = fmaf(wv0.w, f, acc[j][3]);
            acc[j][4] = fmaf(wv1.x, f, acc[j][4]);
            acc[j][5] = fmaf(wv1.y, f, acc[j][5]);
            acc[j][6] = fmaf(wv1.z, f, acc[j][6]);
            acc[j][7] = fmaf(wv1.w, f, acc[j][7]);
        }
    }
    #pragma unroll
    for (int oi = 0; oi < 8; oi++) {
        int o = og * 8 + oi;
        float bo = __ldg(&b_out[o]);
        #pragma unroll
        for (int j = 0; j < 4; j++) {
            int m = m0 + mi + 32 * j;
            int b = m >> 12;
            int q = m & 4095;
            float v = acc[j][oi] + bo;
            v = v >= 0.f ? v : LRELU_SLOPE * v;
            out[((size_t)(b * 64 + o) << 12) + q] = v;
        }
    }
}

// ---------------- launch ----------------
extern "C" void kernel_launch(void* const* d_in, const int* in_sizes, int n_in,
                              void* d_out, int out_size) {
    const float* uv      = (const float*)d_in[0];
    // d_in[1] = feat_2d: shape-only in reference, unused
    const float* feat_3d = (const float*)d_in[2];
    const float* w1      = (const float*)d_in[3];
    const float* b1      = (const float*)d_in[4];
    const float* w2      = (const float*)d_in[5];
    const float* b2      = (const float*)d_in[6];
    const float* w_out   = (const float*)d_in[7];
    const float* b_out   = (const float*)d_in[8];
    float* out = (float*)d_out;

    transpose_f3<<<dim3(NPTS / 32, C_ / 32, BS), dim3(32, 8)>>>(feat_3d);
    bin_points<<<BS, 256>>>(uv);
    knn_search<<<dim3(NCELL, BS), 128>>>();
    score_kernel<<<M_TOT / (QPW * 8), 256>>>(uv, w1, b1, w2, b2);
    out_gemm<<<M_TOT / 128, 256>>>(w_out, b_out, out);
}

// round 7
// speedup vs baseline: 2.4751x; 1.1866x over previous
#include <cuda_runtime.h>
#include <math.h>

// Fixed problem shapes
#define BS     4
#define C_     64
#define H_     64
#define W_     64
#define HW     4096     // H*W
#define NPTS   4096
#define M_TOT  (BS*HW)  // 16384

#define CELL   4
#define GRIDC  16       // 64/CELL
#define NCELL  (GRIDC*GRIDC)
#define CAND_CAP 768    // smem candidate cap (expected ~144)

#define LRELU_SLOPE 0.1f

// ---------------- device scratch (no allocations allowed) ----------------
__device__ float  g_f3t[BS * NPTS * C_];       // feat_3d transposed [b][n][c] (4 MB)
__device__ float4 g_cpts[BS * NPTS];           // binned points (u,v,u2,idx)  (256 KB)
__device__ int    g_cstart[BS][NCELL + 1];     // cell start offsets
__device__ int    g_knn[M_TOT * 3];            // knn indices

// ---------------- K1: prep = transpose feat_3d + bin points ----------------
// blocks [0,1024): transpose (b,C,N)->(b,N,C);  blocks [1024,1028): binning
__global__ void prep(const float* __restrict__ f3, const float* __restrict__ uv) {
    __shared__ float tile[32][33];            // transpose path
    __shared__ int cnt[NCELL], off[NCELL];    // bin path
    __shared__ int sA[NCELL], sB[NCELL];
    int t = threadIdx.x;                      // 256

    if (blockIdx.x < 1024) {
        int bid = blockIdx.x;
        int b   = bid >> 8;                   // 4
        int rem = bid & 255;
        int c0  = (rem >> 7) * 32;            // 2 c-tiles
        int n0  = (rem & 127) * 32;           // 128 n-tiles
        int tx = t & 31, ty = t >> 5;         // 32 x 8
        const float* src = f3 + ((size_t)(b * C_ + c0)) * NPTS + n0;
        #pragma unroll
        for (int i = ty; i < 32; i += 8)
            tile[i][tx] = src[i * NPTS + tx];
        __syncthreads();
        float* dst = g_f3t + ((size_t)(b * NPTS + n0)) * C_ + c0;
        #pragma unroll
        for (int i = ty; i < 32; i += 8)
            dst[i * C_ + tx] = tile[tx][i];
        return;
    }

    // ---- binning: one block per batch ----
    int b = blockIdx.x - 1024;
    const float* uvb = uv + (size_t)b * 2 * NPTS;

    cnt[t] = 0;
    __syncthreads();

    int mycell[16];
    #pragma unroll
    for (int i = 0; i < 16; i++) {
        int n = t + i * 256;
        float u = uvb[n], v = uvb[NPTS + n];
        int cx = (int)(u * 0.25f);            // exact power-of-2 scale
        int cy = (int)(v * 0.25f);
        int c = cy * GRIDC + cx;
        mycell[i] = c;
        atomicAdd(&cnt[c], 1);
    }
    __syncthreads();

    // inclusive scan (Hillis-Steele, double buffer)
    sA[t] = cnt[t];
    __syncthreads();
    int* srcp = sA; int* dstp = sB;
    #pragma unroll
    for (int ofs = 1; ofs < NCELL; ofs <<= 1) {
        int v = srcp[t];
        if (t >= ofs) v += srcp[t - ofs];
        dstp[t] = v;
        __syncthreads();
        int* tmp = srcp; srcp = dstp; dstp = tmp;
    }
    int excl = srcp[t] - cnt[t];
    off[t] = excl;
    g_cstart[b][t] = excl;
    if (t == NCELL - 1) g_cstart[b][NCELL] = srcp[NCELL - 1];
    __syncthreads();

    #pragma unroll
    for (int i = 0; i < 16; i++) {
        int n = t + i * 256;
        int c = mycell[i];
        int pos = atomicAdd(&off[c], 1);
        float u = uvb[n], v = uvb[NPTS + n];
        g_cpts[(size_t)b * NPTS + pos] =
            make_float4(u, v,
                        __fadd_rn(__fmul_rn(u, u), __fmul_rn(v, v)),
                        __int_as_float(n));
    }
}

// ---------------- K2: warp-cooperative KNN ----------------
// One block per (b, cell): 16 queries, 8 threads each.
// d rounding identical to validated version:
//   cross = fma(fy, v, rn(fx*u)); d = rn(rn(g2+u2) - rn(2*cross))
// Selection: (d, idx) lexicographic -> order-independent, matches top_k ties.
#define INS(dv, iv)                                                     \
    if ((dv) < d2 || ((dv) == d2 && (iv) < i2)) {                       \
        if ((dv) < d1 || ((dv) == d1 && (iv) < i1)) {                   \
            d2 = d1; i2 = i1;                                           \
            if ((dv) < d0 || ((dv) == d0 && (iv) < i0)) {               \
                d1 = d0; i1 = i0; d0 = (dv); i0 = (iv);                 \
            } else { d1 = (dv); i1 = (iv); }                            \
        } else { d2 = (dv); i2 = (iv); }                                \
    }

__global__ void knn_search() {
    __shared__ float4 cand[CAND_CAP];
    __shared__ int s_total;

    int b    = blockIdx.y;
    int cell = blockIdx.x;
    int cx = cell & (GRIDC - 1), cy = cell >> 4;
    int tid = threadIdx.x;          // 128

    const float4* pts = g_cpts + (size_t)b * NPTS;
    const int*    cs  = g_cstart[b];

    // ---- stage 3x3 neighborhood into smem ----
    int xlo = max(cx - 1, 0), xhi = min(cx + 1, GRIDC - 1);
    int ylo = max(cy - 1, 0), yhi = min(cy + 1, GRIDC - 1);
    int rs[3], rc_[3], rb[3], nrows = 0, total = 0;
    for (int y = ylo; y <= yhi; y++) {
        int s = cs[y * GRIDC + xlo];
        int e = cs[y * GRIDC + xhi + 1];
        rs[nrows] = s; rc_[nrows] = e - s; rb[nrows] = total;
        total += e - s; nrows++;
    }
    bool fits = (total <= CAND_CAP);
    if (fits) {
        for (int k = 0; k < nrows; k++)
            for (int i = tid; i < rc_[k]; i += 128)
                cand[rb[k] + i] = pts[rs[k] + i];
    }
    if (tid == 0) s_total = total;
    __syncthreads();

    // ---- per-query scan: group g = query, 8 threads/query ----
    int g   = tid >> 3;             // 0..15
    int sub = tid & 7;
    int px = cx * CELL + (g & 3);
    int py = cy * CELL + (g >> 2);
    float fx = (float)px, fy = (float)py;
    float g2 = fx * fx + fy * fy;   // exact (small ints)

    float d0 = 3.4e38f, d1 = 3.4e38f, d2 = 3.4e38f;
    int   i0 = 0x7fffffff, i1 = 0x7fffffff, i2 = 0x7fffffff;

    if (fits) {
        int T = s_total;
        for (int p = sub; p < T; p += 8) {
            float4 P = cand[p];
            float cross = __fmaf_rn(fy, P.y, __fmul_rn(fx, P.x));
            float d = __fsub_rn(__fadd_rn(g2, P.z), __fadd_rn(cross, cross));
            int idx = __float_as_int(P.w);
            INS(d, idx);
        }
    } else {
        // overflow slow path: scan gmem ranges directly (never hit in practice)
        for (int k = 0; k < nrows; k++)
            for (int p = sub; p < rc_[k]; p += 8) {
                float4 P = pts[rs[k] + p];
                float cross = __fmaf_rn(fy, P.y, __fmul_rn(fx, P.x));
                float d = __fsub_rn(__fadd_rn(g2, P.z), __fadd_rn(cross, cross));
                int idx = __float_as_int(P.w);
                INS(d, idx);
            }
    }

    // ---- merge 8 partial top-3 lists (shfl-down tree, width 8) ----
    #pragma unroll
    for (int off = 4; off > 0; off >>= 1) {
        float e0 = __shfl_down_sync(0xffffffffu, d0, off, 8);
        int   j0 = __shfl_down_sync(0xffffffffu, i0, off, 8);
        float e1 = __shfl_down_sync(0xffffffffu, d1, off, 8);
        int   j1 = __shfl_down_sync(0xffffffffu, i1, off, 8);
        float e2 = __shfl_down_sync(0xffffffffu, d2, off, 8);
        int   j2 = __shfl_down_sync(0xffffffffu, i2, off, 8);
        INS(e0, j0);
        INS(e1, j1);
        INS(e2, j2);
    }

    if (sub == 0) {
        // ---- rare fallback: rings >= 2, same bound as validated version ----
        for (int rc = 2; rc < GRIDC; rc++) {
            float lb = (float)(CELL * (rc - 1));
            if (lb * lb > d2 + 0.5f) break;   // false while d2 = INF
            int Xlo = max(cx - rc, 0), Xhi = min(cx + rc, GRIDC - 1);
            int Ylo = max(cy - rc, 0), Yhi = min(cy + rc, GRIDC - 1);
            for (int y = Ylo; y <= Yhi; y++) {
                if (y == cy - rc || y == cy + rc) {
                    int ps = cs[y * GRIDC + Xlo], pe = cs[y * GRIDC + Xhi + 1];
                    for (int p = ps; p < pe; p++) {
                        float4 P = pts[p];
                        float cross = __fmaf_rn(fy, P.y, __fmul_rn(fx, P.x));
                        float d = __fsub_rn(__fadd_rn(g2, P.z), __fadd_rn(cross, cross));
                        int idx = __float_as_int(P.w);
                        INS(d, idx);
                    }
                } else {
                    if (cx - rc >= 0) {
                        int c = y * GRIDC + (cx - rc);
                        for (int p = cs[c]; p < cs[c + 1]; p++) {
                            float4 P = pts[p];
                            float cross = __fmaf_rn(fy, P.y, __fmul_rn(fx, P.x));
                            float d = __fsub_rn(__fadd_rn(g2, P.z), __fadd_rn(cross, cross));
                            int idx = __float_as_int(P.w);
                            INS(d, idx);
                        }
                    }
                    if (cx + rc <= GRIDC - 1) {
                        int c = y * GRIDC + (cx + rc);
                        for (int p = cs[c]; p < cs[c + 1]; p++) {
                            float4 P = pts[p];
                            float cross = __fmaf_rn(fy, P.y, __fmul_rn(fx, P.x));
                            float d = __fsub_rn(__fadd_rn(g2, P.z), __fadd_rn(cross, cross));
                            int idx = __float_as_int(P.w);
                            INS(d, idx);
                        }
                    }
                }
            }
        }
        int m = b * HW + py * 64 + px;
        g_knn[m * 3] = i0; g_knn[m * 3 + 1] = i1; g_knn[m * 3 + 2] = i2;
    }
}
#undef INS

// ---------------- K3: fused score MLP + gather + out GEMM ----------------
// 256 blocks x 256 threads; each block owns 64 queries (m-tile).
// Phase 1 (per warp, 8 queries, R2 shfl z-path): write flo/fhi into swizzled Fs.
// Phase 2: register-tiled GEMM out = lrelu(w_out @ F + b_out) from smem.
__global__ void fused_score_gemm(const float* __restrict__ uv,
                                 const float* __restrict__ w1, const float* __restrict__ b1,
                                 const float* __restrict__ w2, const float* __restrict__ b2,
                                 const float* __restrict__ w_out,
                                 const float* __restrict__ b_out,
                                 float* __restrict__ out) {
    __shared__ float Wt[64 * 64];     // [c][o] for LDS.128 reads
    __shared__ float Fs[64 * 64];     // swizzled: row r, col (c+r)&63

    int tid  = threadIdx.x;
    int lane = tid & 31;
    int wid  = tid >> 5;              // 8 warps
    int m0   = blockIdx.x * 64;

    // stage W transpose (independent of score phase)
    for (int idx = tid; idx < 4096; idx += 256) {
        int o = idx >> 6, c = idx & 63;
        Wt[c * 64 + o] = w_out[idx];
    }

    // ---- phase 1: score (R2 shfl variant, QPW=8) ----
    int i_mine = lane & 15;
    int j_mine = lane >> 4;
    float w1a = w1[i_mine * 3 + 0];
    float w1b = w1[i_mine * 3 + 1];
    float w1c = w1[i_mine * 3 + 2];
    float b1r = b1[i_mine];
    float w2lo[16], w2hi[16];
    #pragma unroll
    for (int i = 0; i < 16; i++) {
        w2lo[i] = w2[lane * 16 + i];
        w2hi[i] = w2[(lane + 32) * 16 + i];
    }
    float b2lo = b2[lane], b2hi = b2[lane + 32];

    int base_m = m0 + wid * 8;
    #pragma unroll
    for (int t = 0; t < 8; t++) {
        int m = base_m + t;                // 0..16383
        int b = m >> 12;
        int q = m & 4095;
        float fx = (float)(q & 63);
        float fy = (float)(q >> 6);

        int n0 = __ldg(&g_knn[m * 3]);
        int n1 = __ldg(&g_knn[m * 3 + 1]);
        int n2 = __ldg(&g_knn[m * 3 + 2]);
        const float* uvb = uv + (size_t)b * 2 * NPTS;

        // feature gathers (coalesced per warp; independent of MLP chain)
        const float* f0 = g_f3t + ((size_t)(b * NPTS + n0)) * C_;
        const float* f1 = g_f3t + ((size_t)(b * NPTS + n1)) * C_;
        const float* f2 = g_f3t + ((size_t)(b * NPTS + n2)) * C_;
        float f0lo = f0[lane], f0hi = f0[lane + 32];
        float f1lo = f1[lane], f1hi = f1[lane + 32];
        float f2lo = f2[lane], f2hi = f2[lane + 32];

        // h for my (i_mine, j_mine) neighbor
        int   na = j_mine ? n1 : n0;
        float ua = uvb[na], va = uvb[NPTS + na];
        float oxa = ua - fx, oya = va - fy;
        float nrma = sqrtf(oxa * oxa + oya * oya);
        float ha = fmaf(w1c, nrma, fmaf(w1b, oya, w1a * oxa)) + b1r;
        ha = ha >= 0.f ? ha : LRELU_SLOPE * ha;
        // h for (i_mine, j=2)
        float ub = uvb[n2], vb = uvb[NPTS + n2];
        float oxb = ub - fx, oyb = vb - fy;
        float nrmb = sqrtf(oxb * oxb + oyb * oyb);
        float hb = fmaf(w1c, nrmb, fmaf(w1b, oyb, w1a * oxb)) + b1r;
        hb = hb >= 0.f ? hb : LRELU_SLOPE * hb;

        float zlo0 = b2lo, zlo1 = b2lo, zlo2 = b2lo;
        float zhi0 = b2hi, zhi1 = b2hi, zhi2 = b2hi;
        #pragma unroll
        for (int i = 0; i < 16; i++) {
            float h0 = __shfl_sync(0xffffffffu, ha, i);
            float h1 = __shfl_sync(0xffffffffu, ha, 16 + i);
            float h2 = __shfl_sync(0xffffffffu, hb, i);
            zlo0 = fmaf(w2lo[i], h0, zlo0);
            zlo1 = fmaf(w2lo[i], h1, zlo1);
            zlo2 = fmaf(w2lo[i], h2, zlo2);
            zhi0 = fmaf(w2hi[i], h0, zhi0);
            zhi1 = fmaf(w2hi[i], h1, zhi1);
            zhi2 = fmaf(w2hi[i], h2, zhi2);
        }
        float s0lo = 1.f / (1.f + __expf(-zlo0));
        float s1lo = 1.f / (1.f + __expf(-zlo1));
        float s2lo = 1.f / (1.f + __expf(-zlo2));
        float s0hi = 1.f / (1.f + __expf(-zhi0));
        float s1hi = 1.f / (1.f + __expf(-zhi1));
        float s2hi = 1.f / (1.f + __expf(-zhi2));

        float flo = fmaf(s2lo, f2lo, fmaf(s1lo, f1lo, s0lo * f0lo));
        float fhi = fmaf(s2hi, f2hi, fmaf(s1hi, f1hi, s0hi * f0hi));

        int r = wid * 8 + t;               // row within tile
        Fs[r * 64 + ((lane + r) & 63)]      = flo;
        Fs[r * 64 + ((lane + 32 + r) & 63)] = fhi;
    }
    __syncthreads();

    // ---- phase 2: GEMM (64 rows x 64 out-channels) ----
    int mi = lane;
    int og = wid;                     // uniform per warp -> broadcast LDS for W
    float acc[2][8];
    #pragma unroll
    for (int j = 0; j < 2; j++)
        #pragma unroll
        for (int oi = 0; oi < 8; oi++) acc[j][oi] = 0.f;

    #pragma unroll 8
    for (int c = 0; c < 64; c++) {
        float4 wv0 = *(const float4*)&Wt[c * 64 + og * 8];
        float4 wv1 = *(const float4*)&Wt[c * 64 + og * 8 + 4];
        #pragma unroll
        for (int j = 0; j < 2; j++) {
            int r = mi + 32 * j;
            float f = Fs[r * 64 + ((c + r) & 63)];
            acc[j][0] = fmaf(wv0.x, f, acc[j][0]);
            acc[j][1] = fmaf(wv0.y, f, acc[j][1]);
            acc[j][2] = fmaf(wv0.z, f, acc[j][2]);
            acc[j][3] = fmaf(wv0.w, f, acc[j][3]);
            acc[j][4] = fmaf(wv1.x, f, acc[j][4]);
            acc[j][5] = fmaf(wv1.y, f, acc[j][5]);
            acc[j][6] = fmaf(wv1.z, f, acc[j][6]);
            acc[j][7] = fmaf(wv1.w, f, acc[j][7]);
        }
    }
    #pragma unroll
    for (int oi = 0; oi < 8; oi++) {
        int o = og * 8 + oi;
        float bo = __ldg(&b_out[o]);
        #pragma unroll
        for (int j = 0; j < 2; j++) {
            int m = m0 + mi + 32 * j;
            int b = m >> 12;
            int q = m & 4095;
            float v = acc[j][oi] + bo;
            v = v >= 0.f ? v : LRELU_SLOPE * v;
            out[((size_t)(b * 64 + o) << 12) + q] = v;
        }
    }
}

// ---------------- launch ----------------
extern "C" void kernel_launch(void* const* d_in, const int* in_sizes, int n_in,
                              void* d_out, int out_size) {
    const float* uv      = (const float*)d_in[0];
    // d_in[1] = feat_2d: shape-only in reference, unused
    const float* feat_3d = (const float*)d_in[2];
    const float* w1      = (const float*)d_in[3];
    const float* b1      = (const float*)d_in[4];
    const float* w2      = (const float*)d_in[5];
    const float* b2      = (const float*)d_in[6];
    const float* w_out   = (const float*)d_in[7];
    const float* b_out   = (const float*)d_in[8];
    float* out = (float*)d_out;

    prep<<<1024 + BS, 256>>>(feat_3d, uv);
    knn_search<<<dim3(NCELL, BS), 128>>>();
    fused_score_gemm<<<M_TOT / 64, 256>>>(uv, w1, b1, w2, b2, w_out, b_out, out);
}